// round 2
// baseline (speedup 1.0000x reference)
#include <cuda_runtime.h>

#define B_ 4
#define N_ 4096
#define C_ 256
#define NSPLIT 32
#define M_ (B_*N_)          // 16384 rows total

typedef unsigned long long ull;

// ------------------------ device scratch (no allocs allowed) ------------------
__device__ float g_psum[2*B_*NSPLIT*C_];
__device__ float g_psq [2*B_*NSPLIT*C_];
__device__ float g_mean[2*B_*C_];
__device__ float g_rstd[2*B_*C_];
__device__ float g_Q[M_*C_];
__device__ float g_K[M_*C_];
__device__ float g_V[M_*C_];

// ------------------------ packed f32x2 helpers --------------------------------
__device__ __forceinline__ void fma2(ull& d, ull a, ull b){
    asm("fma.rn.f32x2 %0, %1, %2, %0;" : "+l"(d) : "l"(a), "l"(b));
}
__device__ __forceinline__ ull pack2(float x, float y){
    ull r; asm("mov.b64 %0, {%1, %2};" : "=l"(r) : "f"(x), "f"(y)); return r;
}
__device__ __forceinline__ float2 unpack2(ull v){
    float2 f; asm("mov.b64 {%0, %1}, %2;" : "=f"(f.x), "=f"(f.y) : "l"(v)); return f;
}

// ------------------------ instance-norm statistics ----------------------------
__global__ void k_stats_partial(const float* __restrict__ content,
                                const float* __restrict__ style){
    const float* x = blockIdx.z ? style : content;
    const int b = blockIdx.y, sp = blockIdx.x, c = threadIdx.x;
    const int rows = N_ / NSPLIT;                      // 128
    const float* base = x + (size_t)b*N_*C_ + (size_t)sp*rows*C_ + c;
    float s = 0.f, ss = 0.f;
    #pragma unroll 4
    for (int r = 0; r < rows; r++){
        float v = base[(size_t)r*C_];
        s += v; ss += v*v;
    }
    int idx = ((blockIdx.z*B_ + b)*NSPLIT + sp)*C_ + c;
    g_psum[idx] = s; g_psq[idx] = ss;
}

__global__ void k_stats_final(){
    const int b = blockIdx.x, t = blockIdx.y, c = threadIdx.x;
    float s = 0.f, ss = 0.f;
    #pragma unroll
    for (int sp = 0; sp < NSPLIT; sp++){
        int idx = ((t*B_ + b)*NSPLIT + sp)*C_ + c;
        s += g_psum[idx]; ss += g_psq[idx];
    }
    float mean = s * (1.f/N_);
    float var  = fmaxf(ss * (1.f/N_) - mean*mean, 0.f);
    g_mean[(t*B_ + b)*C_ + c] = mean;
    g_rstd[(t*B_ + b)*C_ + c] = rsqrtf(var + 1e-5f);
}

// ------------------------ fused norm + 1x1 conv GEMM --------------------------
// out = norm(A) @ W + bias   (normt: 0=content stats, 1=style stats, -1=no norm)
__global__ __launch_bounds__(256) void k_gemm(const float* __restrict__ A,
                                              const float* __restrict__ W,
                                              const float* __restrict__ bias,
                                              int normt, int which){
    __shared__ float As[16][68];
    __shared__ float Bs[16][68];
    float* out = (which == 0) ? g_Q : (which == 1) ? g_K : g_V;
    const int tid = threadIdx.x;
    const int tx = tid & 15, ty = tid >> 4;
    const int tm = blockIdx.x << 6, tn = blockIdx.y << 6;
    const int b = tm >> 12;
    const float* meanp = g_mean + (normt > 0 ? B_*C_ : 0) + b*C_;
    const float* rstdp = g_rstd + (normt > 0 ? B_*C_ : 0) + b*C_;
    const int lr = tid >> 2, lk = (tid & 3) << 2;
    const int wk = tid >> 4, wc = (tid & 15) << 2;
    float acc[4][4] = {};

    for (int k0 = 0; k0 < C_; k0 += 16){
        float4 av = *(const float4*)(A + (size_t)(tm + lr)*C_ + k0 + lk);
        if (normt >= 0){
            int cc = k0 + lk;
            av.x = (av.x - meanp[cc+0]) * rstdp[cc+0];
            av.y = (av.y - meanp[cc+1]) * rstdp[cc+1];
            av.z = (av.z - meanp[cc+2]) * rstdp[cc+2];
            av.w = (av.w - meanp[cc+3]) * rstdp[cc+3];
        }
        As[lk+0][lr] = av.x; As[lk+1][lr] = av.y;
        As[lk+2][lr] = av.z; As[lk+3][lr] = av.w;
        *(float4*)&Bs[wk][wc] = *(const float4*)(W + (size_t)(k0 + wk)*C_ + tn + wc);
        __syncthreads();
        #pragma unroll
        for (int kk = 0; kk < 16; kk++){
            float4 a  = *(const float4*)&As[kk][ty << 2];
            float4 bv = *(const float4*)&Bs[kk][tx << 2];
            acc[0][0] += a.x*bv.x; acc[0][1] += a.x*bv.y; acc[0][2] += a.x*bv.z; acc[0][3] += a.x*bv.w;
            acc[1][0] += a.y*bv.x; acc[1][1] += a.y*bv.y; acc[1][2] += a.y*bv.z; acc[1][3] += a.y*bv.w;
            acc[2][0] += a.z*bv.x; acc[2][1] += a.z*bv.y; acc[2][2] += a.z*bv.z; acc[2][3] += a.z*bv.w;
            acc[3][0] += a.w*bv.x; acc[3][1] += a.w*bv.y; acc[3][2] += a.w*bv.z; acc[3][3] += a.w*bv.w;
        }
        __syncthreads();
    }
    float4 bb = *(const float4*)(bias + tn + (tx << 2));
    #pragma unroll
    for (int r = 0; r < 4; r++){
        float4 o;
        o.x = acc[r][0] + bb.x; o.y = acc[r][1] + bb.y;
        o.z = acc[r][2] + bb.z; o.w = acc[r][3] + bb.w;
        *(float4*)(out + (size_t)(tm + (ty << 2) + r)*C_ + tn + (tx << 2)) = o;
    }
}

// ------------------------ l2norm rows of Q and K (in place) -------------------
__global__ void k_l2n(){
    const int w = threadIdx.x >> 5, l = threadIdx.x & 31;
    const size_t rid = (size_t)blockIdx.x * 8 + w;      // 0 .. 2*M_-1
    float* X = (rid < (size_t)M_) ? g_Q : g_K;
    float* p = X + (rid & (M_ - 1)) * C_;
    float4 a = *(float4*)(p + (l << 2));
    float4 c = *(float4*)(p + 128 + (l << 2));
    float ss = a.x*a.x + a.y*a.y + a.z*a.z + a.w*a.w
             + c.x*c.x + c.y*c.y + c.z*c.z + c.w*c.w;
    #pragma unroll
    for (int o = 16; o; o >>= 1) ss += __shfl_xor_sync(0xffffffffu, ss, o);
    float sc = rsqrtf(ss + 1e-12f);
    a.x *= sc; a.y *= sc; a.z *= sc; a.w *= sc;
    c.x *= sc; c.y *= sc; c.z *= sc; c.w *= sc;
    *(float4*)(p + (l << 2)) = a;
    *(float4*)(p + 128 + (l << 2)) = c;
}

// ------------------------ fused cosine attention + AdaIN ----------------------
// One CTA = 32 queries of one batch. Streams 32-key tiles.
// smem: Qs(32KB,swz) Ks(32KB,swz) Vs(32KB) V2(32KB) Es(32x33)
__global__ __launch_bounds__(256, 1) void k_attn(const float* __restrict__ content,
                                                 float* __restrict__ out){
    extern __shared__ float sm[];
    float* Qs = sm;
    float* Ks = sm + 8192;
    float* Vs = sm + 16384;
    float* V2 = sm + 24576;
    float* Es = sm + 32768;            // 32*33 floats

    const int tid = threadIdx.x;
    const int q = tid >> 3, g = tid & 7;
    const int q0 = blockIdx.x << 5;    // global query row
    const int b = q0 >> 12;
    const int kbase = b << 12;

    // load + swizzle Q tile (rows q0..q0+31)
    for (int it = tid; it < 2048; it += 256){
        int r = it >> 6, c4 = it & 63;
        float4 v = *(const float4*)(g_Q + (size_t)(q0 + r)*C_ + (c4 << 2));
        *(float4*)&Qs[((r << 6) + (c4 ^ (r & 7))) << 2] = v;
    }

    ull acc[16], ac2[16];
    #pragma unroll
    for (int i = 0; i < 16; i++){ acc[i] = 0ull; ac2[i] = 0ull; }
    float Z = 0.f;

    const ulonglong2* Qs4 = (const ulonglong2*)Qs;
    const ulonglong2* Ks4 = (const ulonglong2*)Ks;
    const ulonglong2* Vs4 = (const ulonglong2*)Vs;
    const ulonglong2* V24 = (const ulonglong2*)V2;
    const int qsw = q & 7;

    for (int kt = 0; kt < N_/32; kt++){
        __syncthreads();
        const size_t krow0 = (size_t)(kbase + (kt << 5));
        for (int it = tid; it < 2048; it += 256){
            int r = it >> 6, c4 = it & 63;
            size_t off = (krow0 + r)*C_ + (c4 << 2);
            *(float4*)&Ks[((r << 6) + (c4 ^ (r & 7))) << 2] = *(const float4*)(g_K + off);
            *(float4*)&Vs[it << 2] = *(const float4*)(g_V + off);
        }
        __syncthreads();

        // V^2 tile
        for (int it = tid; it < 2048; it += 256){
            float4 v = *(const float4*)&Vs[it << 2];
            v.x *= v.x; v.y *= v.y; v.z *= v.z; v.w *= v.w;
            *(float4*)&V2[it << 2] = v;
        }

        // logits: thread computes 4 logits (q, g+8jj), packed dot over k
        ull se[4], so[4];
        #pragma unroll
        for (int jj = 0; jj < 4; jj++){ se[jj] = 0ull; so[jj] = 0ull; }
        #pragma unroll 4
        for (int k4 = 0; k4 < 64; k4++){
            ulonglong2 qp = Qs4[(q << 6) + (k4 ^ qsw)];
            #pragma unroll
            for (int jj = 0; jj < 4; jj++){
                ulonglong2 kp = Ks4[((g + (jj << 3)) << 6) + (k4 ^ g)];
                fma2(se[jj], qp.x, kp.x);
                fma2(so[jj], qp.y, kp.y);
            }
        }
        #pragma unroll
        for (int jj = 0; jj < 4; jj++){
            float2 a = unpack2(se[jj]);
            float2 c = unpack2(so[jj]);
            Es[q*33 + g + (jj << 3)] = __expf(a.x + a.y + c.x + c.y);
        }
        __syncthreads();

        // accumulate Z, sum e*V, sum e*V^2 (thread owns channels 4*(g+8i)..+3)
        #pragma unroll 2
        for (int j = 0; j < 32; j++){
            float e = Es[q*33 + j];
            Z += e;
            ull ee = pack2(e, e);
            #pragma unroll
            for (int i = 0; i < 8; i++){
                int idx = (j << 6) + g + (i << 3);
                ulonglong2 v = Vs4[idx];
                ulonglong2 w = V24[idx];
                fma2(acc[2*i],   ee, v.x); fma2(acc[2*i+1], ee, v.y);
                fma2(ac2[2*i],   ee, w.x); fma2(ac2[2*i+1], ee, w.y);
            }
        }
    }

    // epilogue: M = acc/Z, S2 = ac2/Z - M^2, out = sqrt(relu(S2))*norm_content + M
    float invZ = 1.f / Z;
    const float* meanp = g_mean + b*C_;     // content stats (t=0)
    const float* rstdp = g_rstd + b*C_;
    size_t row = (size_t)(q0 + q)*C_;
    #pragma unroll
    for (int i = 0; i < 8; i++){
        int c = (g + (i << 3)) << 2;
        float2 m0 = unpack2(acc[2*i]),  m1 = unpack2(acc[2*i+1]);
        float2 s0 = unpack2(ac2[2*i]),  s1 = unpack2(ac2[2*i+1]);
        float4 cv = *(const float4*)(content + row + c);
        float4 o;
        float m, s2, s, nc;
        m = m0.x*invZ; s2 = s0.x*invZ - m*m; s = s2 > 0.f ? sqrtf(s2) : 0.f;
        nc = (cv.x - meanp[c+0])*rstdp[c+0]; o.x = s*nc + m;
        m = m0.y*invZ; s2 = s0.y*invZ - m*m; s = s2 > 0.f ? sqrtf(s2) : 0.f;
        nc = (cv.y - meanp[c+1])*rstdp[c+1]; o.y = s*nc + m;
        m = m1.x*invZ; s2 = s1.x*invZ - m*m; s = s2 > 0.f ? sqrtf(s2) : 0.f;
        nc = (cv.z - meanp[c+2])*rstdp[c+2]; o.z = s*nc + m;
        m = m1.y*invZ; s2 = s1.y*invZ - m*m; s = s2 > 0.f ? sqrtf(s2) : 0.f;
        nc = (cv.w - meanp[c+3])*rstdp[c+3]; o.w = s*nc + m;
        *(float4*)(out + row + c) = o;
    }
}

// ------------------------ launch ----------------------------------------------
extern "C" void kernel_launch(void* const* d_in, const int* in_sizes, int n_in,
                              void* d_out, int out_size){
    const float* content = (const float*)d_in[0];
    const float* style   = (const float*)d_in[1];
    const float* Wq = (const float*)d_in[2];
    const float* bq = (const float*)d_in[3];
    const float* Wk = (const float*)d_in[4];
    const float* bk = (const float*)d_in[5];
    const float* Wv = (const float*)d_in[6];
    const float* bv = (const float*)d_in[7];
    float* out = (float*)d_out;

    static const int SMEM_ATTN = (8192*4 + 32*33) * 4;   // 135296 bytes
    cudaFuncSetAttribute(k_attn, cudaFuncAttributeMaxDynamicSharedMemorySize, SMEM_ATTN);

    k_stats_partial<<<dim3(NSPLIT, B_, 2), 256>>>(content, style);
    k_stats_final<<<dim3(B_, 2), 256>>>();
    k_gemm<<<dim3(M_/64, C_/64), 256>>>(content, Wq, bq, 0, 0);
    k_gemm<<<dim3(M_/64, C_/64), 256>>>(style,   Wk, bk, 1, 1);
    k_gemm<<<dim3(M_/64, C_/64), 256>>>(style,   Wv, bv, -1, 2);
    k_l2n<<<2*M_/8, 256>>>();
    k_attn<<<M_/32, 256, SMEM_ATTN>>>(content, out);
}